// round 14
// baseline (speedup 1.0000x reference)
#include <cuda_runtime.h>
#include <cuda_bf16.h>

#define H 512
#define W 512
#define OW 510
#define PLANE (H * W)
#define RBLK 2                     // window rows per warp-task
#define WIN_PER_WARP 62            // 31 lanes x 2 windows (even/odd)
#define COLGROUPS 9                // ceil(510 / 62)
#define ROWGROUPS (OW / RBLK)      // 255 exactly
#define NTASKS (ROWGROUPS * COLGROUPS)     // 2295
#define WARPS_PER_BLOCK 5
#define NBLOCKS (NTASKS / WARPS_PER_BLOCK) // 459 exactly

__device__ double       g_accum;   // zero-init; restored to 0 each call
__device__ unsigned int g_cnt;     // zero-init; restored to 0 each call

static __device__ __forceinline__ float2 operator+(float2 a, float2 b){ return make_float2(a.x+b.x, a.y+b.y); }
static __device__ __forceinline__ float2 operator-(float2 a, float2 b){ return make_float2(a.x-b.x, a.y-b.y); }
static __device__ __forceinline__ float2 operator*(float2 a, float2 b){ return make_float2(a.x*b.x, a.y*b.y); }
static __device__ __forceinline__ float2 operator*(float s,  float2 b){ return make_float2(s*b.x,  s*b.y ); }

// build 22 per-column-pair stats from one pixel row (6 float2 channel values)
static __device__ __forceinline__ void make_stats(
    float2 t0, float2 t1, float2 t2, float2 v0, float2 v1, float2 v2, float2 rs[22])
{
    rs[0]  = t0;     rs[1]  = t1;     rs[2]  = t2;
    rs[3]  = v0;     rs[4]  = v1;     rs[5]  = v2;
    rs[6]  = t0*t0;  rs[7]  = t0*t1;  rs[8]  = t0*t2;
    rs[9]  = t1*t1;  rs[10] = t1*t2;  rs[11] = t2*t2;
    rs[12] = v0*v0 + v1*v1 + v2*v2;
    rs[13] = t0*v0;  rs[14] = t0*v1;  rs[15] = t0*v2;
    rs[16] = t1*v0;  rs[17] = t1*v1;  rs[18] = t1*v2;
    rs[19] = t2*v0;  rs[20] = t2*v1;  rs[21] = t2*v2;
}

// transform column-pair stats to (even, odd) window stats, then compute both
// windows' contributions; returns their sum. Destroys cs.
static __device__ __forceinline__ float window_pair_value(float2 cs[22])
{
    // even window (.x): S.x + S.y + Sn.x ; odd window (.y): S.y + Sn.x + Sn.y
    #pragma unroll
    for (int k = 0; k < 22; k++) {
        const float snx = __shfl_down_sync(0xffffffffu, cs[k].x, 1);
        const float sny = __shfl_down_sync(0xffffffffu, cs[k].y, 1);
        const float we  = cs[k].x + cs[k].y + snx;
        const float wo  = cs[k].y + snx + sny;
        cs[k].x = we; cs[k].y = wo;
    }

    const float inv9 = 1.0f / 9.0f;
    const float eps9 = 1e-7f * inv9;
    const float2 e9  = make_float2(eps9, eps9);

    const float2 mu0 = inv9 * cs[0], mu1 = inv9 * cs[1], mu2 = inv9 * cs[2];
    const float2 sV0 = cs[3], sV1 = cs[4], sV2 = cs[5];

    const float2 a00 = inv9*cs[6]  - mu0*mu0 + e9;
    const float2 a01 = inv9*cs[7]  - mu0*mu1;
    const float2 a02 = inv9*cs[8]  - mu0*mu2;
    const float2 a11 = inv9*cs[9]  - mu1*mu1 + e9;
    const float2 a12 = inv9*cs[10] - mu1*mu2;
    const float2 a22 = inv9*cs[11] - mu2*mu2 + e9;

    const float2 c00 = a11*a22 - a12*a12;
    const float2 c01 = a02*a12 - a01*a22;
    const float2 c02 = a01*a12 - a02*a11;
    const float2 c11 = a00*a22 - a02*a02;
    const float2 c12 = a01*a02 - a00*a12;
    const float2 c22 = a00*a11 - a01*a01;
    const float2 det = a00*c00 + a01*c01 + a02*c02;
    const float2 rdet = make_float2(1.0f/det.x, 1.0f/det.y);
    const float2 i00 = c00*rdet, i01 = c01*rdet, i02 = c02*rdet;
    const float2 i11 = c11*rdet, i12 = c12*rdet, i22 = c22*rdet;

    float2 pen = sV0*sV0 + sV1*sV1 + sV2*sV2;

    {   // channel 0
        const float2 u0 = cs[13] - mu0*sV0;
        const float2 u1 = cs[16] - mu1*sV0;
        const float2 u2 = cs[19] - mu2*sV0;
        pen = pen + i00*u0*u0 + i11*u1*u1 + i22*u2*u2
                  + 2.f*(i01*u0*u1 + i02*u0*u2 + i12*u1*u2);
    }
    {   // channel 1
        const float2 u0 = cs[14] - mu0*sV1;
        const float2 u1 = cs[17] - mu1*sV1;
        const float2 u2 = cs[20] - mu2*sV1;
        pen = pen + i00*u0*u0 + i11*u1*u1 + i22*u2*u2
                  + 2.f*(i01*u0*u1 + i02*u0*u2 + i12*u1*u2);
    }
    {   // channel 2
        const float2 u0 = cs[15] - mu0*sV2;
        const float2 u1 = cs[18] - mu1*sV2;
        const float2 u2 = cs[21] - mu2*sV2;
        pen = pen + i00*u0*u0 + i11*u1*u1 + i22*u2*u2
                  + 2.f*(i01*u0*u1 + i02*u0*u2 + i12*u1*u2);
    }

    const float2 val = cs[12] - inv9 * pen;
    return val.x + val.y;
}

static __device__ __forceinline__ void load_row(
    const float* __restrict__ T, const float* __restrict__ V,
    int base, bool ok,
    float2& t0, float2& t1, float2& t2, float2& v0, float2& v1, float2& v2)
{
    const float2 z = make_float2(0.f, 0.f);
    t0 = ok ? *reinterpret_cast<const float2*>(T + 0*PLANE + base) : z;
    t1 = ok ? *reinterpret_cast<const float2*>(T + 1*PLANE + base) : z;
    t2 = ok ? *reinterpret_cast<const float2*>(T + 2*PLANE + base) : z;
    v0 = ok ? *reinterpret_cast<const float2*>(V + 0*PLANE + base) : z;
    v1 = ok ? *reinterpret_cast<const float2*>(V + 1*PLANE + base) : z;
    v2 = ok ? *reinterpret_cast<const float2*>(V + 2*PLANE + base) : z;
}

__global__ __launch_bounds__(WARPS_PER_BLOCK * 32)
void ml_fused_kernel(const float* __restrict__ T, const float* __restrict__ V,
                     float* __restrict__ out)
{
    const int warp_id  = threadIdx.x >> 5;
    const int lane     = threadIdx.x & 31;
    const int warp_gid = blockIdx.x * WARPS_PER_BLOCK + warp_id;

    const int rg = warp_gid / COLGROUPS;          // row group 0..254
    const int cg = warp_gid % COLGROUPS;          // col group 0..8
    const int r0 = rg * RBLK;                     // first window row of task
    const int x0 = cg * WIN_PER_WARP + 2 * lane;  // even pixel column this lane owns

    const bool ld_ok  = (x0 <= 510);              // cols x0, x0+1 exist
    const bool win_ok = (lane < 31) && (x0 <= 508); // both windows valid

    float contrib = 0.0f;

    // shared middle rows r0+1, r0+2
    float2 P[22], tmp[22];
    {
        float2 t0,t1,t2,v0,v1,v2;
        load_row(T, V, (r0 + 1) * W + x0, ld_ok, t0,t1,t2,v0,v1,v2);
        make_stats(t0,t1,t2,v0,v1,v2, P);
        load_row(T, V, (r0 + 2) * W + x0, ld_ok, t0,t1,t2,v0,v1,v2);
        make_stats(t0,t1,t2,v0,v1,v2, tmp);
        #pragma unroll
        for (int k = 0; k < 22; k++) P[k] = P[k] + tmp[k];
    }

    // window row A: pixel rows r0, r0+1, r0+2
    {
        float2 cs[22];
        float2 t0,t1,t2,v0,v1,v2;
        load_row(T, V, r0 * W + x0, ld_ok, t0,t1,t2,v0,v1,v2);
        make_stats(t0,t1,t2,v0,v1,v2, tmp);
        #pragma unroll
        for (int k = 0; k < 22; k++) cs[k] = P[k] + tmp[k];
        const float wv = window_pair_value(cs);
        if (win_ok) contrib += wv;
    }
    // window row B: pixel rows r0+1, r0+2, r0+3
    {
        float2 cs[22];
        float2 t0,t1,t2,v0,v1,v2;
        load_row(T, V, (r0 + 3) * W + x0, ld_ok, t0,t1,t2,v0,v1,v2);
        make_stats(t0,t1,t2,v0,v1,v2, tmp);
        #pragma unroll
        for (int k = 0; k < 22; k++) cs[k] = P[k] + tmp[k];
        const float wv = window_pair_value(cs);
        if (win_ok) contrib += wv;
    }

    // warp reduction
    #pragma unroll
    for (int off = 16; off > 0; off >>= 1)
        contrib += __shfl_xor_sync(0xffffffffu, contrib, off);

    __shared__ float wsum[WARPS_PER_BLOCK];
    __shared__ bool  is_last;
    if (lane == 0) wsum[warp_id] = contrib;
    __syncthreads();

    if (threadIdx.x == 0) {
        float s = 0.f;
        #pragma unroll
        for (int i = 0; i < WARPS_PER_BLOCK; i++) s += wsum[i];
        atomicAdd(&g_accum, (double)s);
        __threadfence();
        unsigned int prev = atomicAdd(&g_cnt, 1u);
        is_last = (prev == NBLOCKS - 1);
    }
    __syncthreads();

    if (is_last && threadIdx.x == 0) {
        __threadfence();
        out[0] = (float)g_accum;
        g_accum = 0.0;
        g_cnt   = 0;
    }
}

extern "C" void kernel_launch(void* const* d_in, const int* in_sizes, int n_in,
                              void* d_out, int out_size)
{
    const float* target = (const float*)d_in[0];
    const float* style  = (const float*)d_in[1];
    float* out = (float*)d_out;

    ml_fused_kernel<<<NBLOCKS, WARPS_PER_BLOCK * 32>>>(target, style, out);
}